// round 16
// baseline (speedup 1.0000x reference)
#include <cuda_runtime.h>
#include <float.h>

// Problem constants (fixed by setup_inputs)
#define B_   16
#define L_   128
#define N_   (B_*L_)      // 2048
#define C_   14
#define E_   256
#define K_   9
#define TI_  8            // i-rows per fused block
#define NT_  256          // threads per block (2 atom-groups x 128 columns)
#define FUSED_BLOCKS (B_ * (L_ / TI_))   // 256
#define EMBED_BLOCKS (N_ / 2)            // 1024
#define BIGF 1e10f
#define POISON 3.0e38f

// Output layout (float32, outputs flattened + concatenated in reference order)
#define OFF_H          0u
#define OFF_CTX_KNN    1048576u
#define OFF_CTX_VALID  1085440u
#define OFF_ADJ        1103872u
#define OFF_INT_KNN    1366016u
#define OFF_INT_VALID  1402880u
#define KNN_ROWS       (N_*K_)   // 18432

__device__ __forceinline__ bool is_glob(int s) { return (s == 21) | (s == 22) | (s == 23); }

// ---- packed f32x2 helpers (per-half IEEE identical to scalar sequence) ----
typedef unsigned long long u64t;
__device__ __forceinline__ u64t pack2(float lo, float hi) {
    u64t r; asm("mov.b64 %0, {%1,%2};" : "=l"(r) : "f"(lo), "f"(hi)); return r;
}
__device__ __forceinline__ void unpack2(u64t p, float& lo, float& hi) {
    asm("mov.b64 {%0,%1}, %2;" : "=f"(lo), "=f"(hi) : "l"(p));
}
__device__ __forceinline__ u64t mul2(u64t a, u64t b) {
    u64t r; asm("mul.rn.f32x2 %0, %1, %2;" : "=l"(r) : "l"(a), "l"(b)); return r;
}
__device__ __forceinline__ u64t add2(u64t a, u64t b) {
    u64t r; asm("add.rn.f32x2 %0, %1, %2;" : "=l"(r) : "l"(a), "l"(b)); return r;
}
__device__ __forceinline__ u64t fma2(u64t a, u64t b, u64t c) {
    u64t r; asm("fma.rn.f32x2 %0, %1, %2, %3;" : "=l"(r) : "l"(a), "l"(b), "l"(c)); return r;
}

struct SmemFused {
    __align__(16) u64t sdup[TI_ * C_ * 4];  // {v,v} broadcast operands per (ii,c)
    float sraw[42 * 129];         // [r=c*3+d][j], pitch 129 (transpose pad)
    float ssq [C_ * L_];          // [c][j], poisoned if atom invalid
    float spart[2][TI_][L_];      // partial min d2 per atom-group
    int   sS[L_], sSeg[L_];
};
struct SmemEmbed {
    int sA[2][C_], sAP[2][C_];
};
union SmemAll { SmemFused f; SmemEmbed e; };

// ---------------------------------------------------------------------------
// Single kernel; blockIdx < FUSED_BLOCKS -> dist+knn+adj, else -> embed x2.
// ---------------------------------------------------------------------------
__global__ void __launch_bounds__(NT_, 4) mono_kernel(
        const float* __restrict__ X, const int* __restrict__ AP,
        const int* __restrict__ S, const int* __restrict__ seg,
        const int* __restrict__ RP, const int* __restrict__ A,
        const float* __restrict__ res_e, const float* __restrict__ atom_e,
        const float* __restrict__ atom_pe,
        float* __restrict__ out)
{
    __shared__ SmemAll sm;
    const int t = threadIdx.x;

    if (blockIdx.x >= FUSED_BLOCKS) {
        // ========== EMBED: 2 residues/block, thread = channel pair ==========
        const int nb   = blockIdx.x - FUSED_BLOCKS;
        const int half = t >> 7;
        const int e    = t & 127;                 // channel-pair index 0..127
        const int n    = nb * 2 + half;
        if (e < C_) { sm.e.sA[half][e] = A[n*C_ + e]; sm.e.sAP[half][e] = AP[n*C_ + e]; }
        __syncthreads();
        int cnt = 0;
        #pragma unroll
        for (int c = 0; c < C_; c++) cnt += (sm.e.sAP[half][c] != 0);
        float den = (float)cnt + 1e-10f;

        int   s  = S[n];
        float rp = (float)RP[n];
        float inv = exp2f(-(float)e * (13.287712379549449f / 128.0f));
        float ang = rp * inv;
        float sv, cv;
        __sincosf(ang, &sv, &cv);
        float2 re2 = *(const float2*)&res_e[s * E_ + 2*e];
        float2 o0; o0.x = re2.x + sv; o0.y = re2.y + cv;
        *(float2*)&out[OFF_H + (unsigned)n * 512u + 2*e] = o0;

        float accx = 0.0f, accy = 0.0f;
        #pragma unroll
        for (int c = 0; c < C_; c++) {
            int ap = sm.e.sAP[half][c];
            if (ap != 0) {
                float2 ae2 = *(const float2*)&atom_e [sm.e.sA[half][c] * E_ + 2*e];
                float2 pe2 = *(const float2*)&atom_pe[ap * E_ + 2*e];
                accx += ae2.x + pe2.x;
                accy += ae2.y + pe2.y;
            }
        }
        float2 o1; o1.x = accx / den; o1.y = accy / den;
        *(float2*)&out[OFF_H + (unsigned)n * 512u + 256u + 2*e] = o1;
        return;
    }

    // ================= FUSED dist + knn + adj ===============================
    const int b  = blockIdx.x / (L_ / TI_);
    const int i0 = (blockIdx.x % (L_ / TI_)) * TI_;
    const int g  = t >> 7;          // atom-group: 0 -> atoms 0..7, 1 -> atoms 8..13
    const int j  = t & 127;         // column
    const int lane = t & 31;
    const int wid  = t >> 5;

    // --- staging: coalesced read of whole batch coords -> padded transpose ---
    const float* Xb = X + (size_t)b * L_ * C_ * 3;
    #pragma unroll
    for (int k = 0; k < 21; k++) {
        int idx = k * NT_ + t;               // 21*256 = 5376 = L_*C_*3
        int jj  = idx / 42;
        int r   = idx - jj * 42;
        sm.f.sraw[r * 129 + jj] = Xb[idx];
    }
    if (t < L_) {
        sm.f.sS[t]   = S[b * L_ + t];
        sm.f.sSeg[t] = seg[b * L_ + t];
    }
    __syncthreads();

    // --- per (group, column): own 4 atom-pairs into packed registers; ssq to smem ---
    u64t y0p[4], y1p[4], y2p[4], sjp[4];
    {
        const int cbase = g * 8;
        const int* apRow = AP + ((size_t)b * L_ + j) * C_;
        #pragma unroll
        for (int p = 0; p < 4; p++) {
            float a0l=0.f,a1l=0.f,a2l=0.f,sql=POISON;
            float a0h=0.f,a1h=0.f,a2h=0.f,sqh=POISON;
            int c0 = cbase + 2*p, c1 = c0 + 1;
            if (c0 < C_) {
                a0l = sm.f.sraw[(3*c0+0)*129 + j];
                a1l = sm.f.sraw[(3*c0+1)*129 + j];
                a2l = sm.f.sraw[(3*c0+2)*129 + j];
                float sq = (a0l*a0l + a1l*a1l) + a2l*a2l;
                sql = (apRow[c0] != 0) ? sq : POISON;
                sm.f.ssq[c0 * L_ + j] = sql;
            }
            if (c1 < C_) {
                a0h = sm.f.sraw[(3*c1+0)*129 + j];
                a1h = sm.f.sraw[(3*c1+1)*129 + j];
                a2h = sm.f.sraw[(3*c1+2)*129 + j];
                float sq = (a0h*a0h + a1h*a1h) + a2h*a2h;
                sqh = (apRow[c1] != 0) ? sq : POISON;
                sm.f.ssq[c1 * L_ + j] = sqh;
            }
            y0p[p] = pack2(a0l, a0h);
            y1p[p] = pack2(a1l, a1h);
            y2p[p] = pack2(a2l, a2h);
            sjp[p] = pack2(sql, sqh);
        }
    }
    __syncthreads();

    // --- build duplicated broadcast operands for the TI_ i-rows ---
    if (t < TI_ * C_) {
        int ii = t / C_, c = t % C_;
        int i  = i0 + ii;
        float v0 = sm.f.sraw[(3*c+0)*129 + i];
        float v1 = sm.f.sraw[(3*c+1)*129 + i];
        float v2 = sm.f.sraw[(3*c+2)*129 + i];
        float sq = sm.f.ssq[c * L_ + i];
        u64t* d = &sm.f.sdup[(ii * C_ + c) * 4];
        d[0] = pack2(v0, v0); d[1] = pack2(v1, v1);
        d[2] = pack2(v2, v2); d[3] = pack2(sq, sq);
    }
    __syncthreads();

    // --- hot loop: partial min over this group's atom pairs ---
    const u64t negtwo = pack2(-2.0f, -2.0f);
    #pragma unroll 2
    for (int ii = 0; ii < TI_; ii++) {
        float b0 = FLT_MAX, b1 = FLT_MAX, b2 = FLT_MAX, b3 = FLT_MAX;
        const ulonglong2* dup = (const ulonglong2*)&sm.f.sdup[ii * C_ * 4];
        #pragma unroll
        for (int c = 0; c < C_; c++) {
            ulonglong2 dA = dup[c*2 + 0];    // {xi0p, xi1p}  LDS.128 broadcast
            ulonglong2 dB = dup[c*2 + 1];    // {xi2p, sqcp}
            u64t xi0p = dA.x, xi1p = dA.y, xi2p = dB.x, sqcp = dB.y;
            #pragma unroll
            for (int p = 0; p < 4; p += 2) {
                {
                    u64t dot = fma2(xi2p, y2p[p], fma2(xi1p, y1p[p], mul2(xi0p, y0p[p])));
                    u64t d2  = fma2(dot, negtwo, add2(sqcp, sjp[p]));
                    float lo, hi;
                    unpack2(d2, lo, hi);          // register aliasing, no SASS op
                    b0 = fminf(b0, lo);
                    b1 = fminf(b1, hi);
                }
                {
                    u64t dot = fma2(xi2p, y2p[p+1], fma2(xi1p, y1p[p+1], mul2(xi0p, y0p[p+1])));
                    u64t d2  = fma2(dot, negtwo, add2(sqcp, sjp[p+1]));
                    float lo, hi;
                    unpack2(d2, lo, hi);
                    b2 = fminf(b2, lo);
                    b3 = fminf(b3, hi);
                }
            }
        }
        sm.f.spart[g][ii][j] = fminf(fminf(b0, b1), fminf(b2, b3));
    }

    // --- adj rows: thread (g, j) handles rows i0 + 4g .. i0 + 4g + 3 ---
    {
        bool gj = is_glob(sm.f.sS[j]);
        int  segj = sm.f.sSeg[j];
        #pragma unroll
        for (int r2 = 0; r2 < 4; r2++) {
            int i = i0 + g * 4 + r2;
            bool gi = is_glob(sm.f.sS[i]);
            bool same = (sm.f.sSeg[i] == segj);
            bool ns   = (i != j);
            bool gn = same && (gi || gj) && ns;
            bool gg = gi && gj && ns;
            int  d  = i - j; if (d < 0) d = -d;
            bool sme = (d == 1) && !gi && !gj && (sm.f.sSeg[i] != 1);
            out[OFF_ADJ + ((unsigned)(b * L_ + i)) * L_ + j] = (gn || gg || sme) ? 1.0f : 0.0f;
        }
    }
    __syncthreads();

    // --- knn: 2*TI_ = 16 warp tasks, 8 warps x 2 rounds (REDUX argmin) ---
    const unsigned BIGB = __float_as_uint(BIGF);
    #pragma unroll
    for (int round = 0; round < 2; round++) {
        int tt   = wid + round * 8;
        int ii   = tt >> 1;
        int type = tt & 1;                  // 0 = ctx (inner), 1 = inter (outer)
        int i    = i0 + ii;
        int r    = b * L_ + i;
        bool gi  = is_glob(sm.f.sS[i]);
        int  si  = sm.f.sSeg[i];

        unsigned u0, u1, u2, u3;
        {
            unsigned uu[4];
            #pragma unroll
            for (int s2 = 0; s2 < 4; s2++) {
                int jj = lane + 32 * s2;
                bool gj   = is_glob(sm.f.sS[jj]);
                bool same = (sm.f.sSeg[jj] == si);
                bool m;
                if (type == 0) m = same && !gi && !gj && (jj != i);
                else           m = !same && !gi && !gj;
                float d2 = fminf(sm.f.spart[0][ii][jj], sm.f.spart[1][ii][jj]);
                float dv = sqrtf(fmaxf(d2, 0.0f));
                uu[s2] = m ? __float_as_uint(dv) : BIGB;
            }
            u0 = uu[0]; u1 = uu[1]; u2 = uu[2]; u3 = uu[3];
        }

        unsigned offK = type ? OFF_INT_KNN   : OFF_CTX_KNN;
        unsigned offV = type ? OFF_INT_VALID : OFF_CTX_VALID;

        #pragma unroll
        for (int k = 0; k < K_; k++) {
            unsigned m    = min(min(u0, u1), min(u2, u3));
            unsigned wmin = __reduce_min_sync(0xffffffffu, m);
            unsigned jc = 256u;
            if (u3 == wmin) jc = (unsigned)lane + 96u;
            if (u2 == wmin) jc = (unsigned)lane + 64u;
            if (u1 == wmin) jc = (unsigned)lane + 32u;
            if (u0 == wmin) jc = (unsigned)lane;
            unsigned jw = __reduce_min_sync(0xffffffffu, jc);
            unsigned s  = jw >> 5;
            bool own = (jc == jw);
            u0 = (own && s == 0u) ? 0xFFFFFFFFu : u0;
            u1 = (own && s == 1u) ? 0xFFFFFFFFu : u1;
            u2 = (own && s == 2u) ? 0xFFFFFFFFu : u2;
            u3 = (own && s == 3u) ? 0xFFFFFFFFu : u3;
            if (lane == 0) {
                bool valid = wmin < BIGB;
                out[offK + (unsigned)r * K_ + k]            = valid ? (float)r                : -1.0f;
                out[offK + KNN_ROWS + (unsigned)r * K_ + k] = valid ? (float)(b*L_ + (int)jw) : -1.0f;
                out[offV + (unsigned)r * K_ + k]            = valid ? 1.0f : 0.0f;
            }
        }
    }
}

// ---------------------------------------------------------------------------
extern "C" void kernel_launch(void* const* d_in, const int* in_sizes, int n_in,
                              void* d_out, int out_size)
{
    const int*   S   = (const int*)  d_in[0];
    const int*   RP  = (const int*)  d_in[1];
    const int*   A   = (const int*)  d_in[2];
    const int*   AP  = (const int*)  d_in[3];
    const float* X   = (const float*)d_in[4];
    const int*   seg = (const int*)  d_in[5];
    const float* re  = (const float*)d_in[6];
    const float* ae  = (const float*)d_in[7];
    const float* ape = (const float*)d_in[8];
    float* out = (float*)d_out;

    mono_kernel<<<FUSED_BLOCKS + EMBED_BLOCKS, NT_>>>(X, AP, S, seg, RP, A, re, ae, ape, out);
}

// round 17
// speedup vs baseline: 1.3273x; 1.3273x over previous
#include <cuda_runtime.h>
#include <float.h>

// Problem constants (fixed by setup_inputs)
#define B_   16
#define L_   128
#define N_   (B_*L_)      // 2048
#define C_   14
#define E_   256
#define K_   9
#define TI_  4            // i-rows per fused block
#define NT_  256          // threads per block (2 atom-groups x 128 columns)
#define FUSED_BLOCKS (B_ * (L_ / TI_))   // 512
#define EMBED_BLOCKS (N_ / 2)            // 1024
#define BIGF 1e10f
#define POISON 3.0e38f

// Output layout (float32, outputs flattened + concatenated in reference order)
#define OFF_H          0u
#define OFF_CTX_KNN    1048576u
#define OFF_CTX_VALID  1085440u
#define OFF_ADJ        1103872u
#define OFF_INT_KNN    1366016u
#define OFF_INT_VALID  1402880u
#define KNN_ROWS       (N_*K_)   // 18432

__device__ __forceinline__ bool is_glob(int s) { return (s == 21) | (s == 22) | (s == 23); }

// ---- packed f32x2 helpers (per-half IEEE identical to scalar sequence) ----
typedef unsigned long long u64t;
__device__ __forceinline__ u64t pack2(float lo, float hi) {
    u64t r; asm("mov.b64 %0, {%1,%2};" : "=l"(r) : "f"(lo), "f"(hi)); return r;
}
__device__ __forceinline__ void unpack2(u64t p, float& lo, float& hi) {
    asm("mov.b64 {%0,%1}, %2;" : "=f"(lo), "=f"(hi) : "l"(p));
}
__device__ __forceinline__ u64t mul2(u64t a, u64t b) {
    u64t r; asm("mul.rn.f32x2 %0, %1, %2;" : "=l"(r) : "l"(a), "l"(b)); return r;
}
__device__ __forceinline__ u64t add2(u64t a, u64t b) {
    u64t r; asm("add.rn.f32x2 %0, %1, %2;" : "=l"(r) : "l"(a), "l"(b)); return r;
}
__device__ __forceinline__ u64t fma2(u64t a, u64t b, u64t c) {
    u64t r; asm("fma.rn.f32x2 %0, %1, %2, %3;" : "=l"(r) : "l"(a), "l"(b), "l"(c)); return r;
}

struct SmemFused {
    __align__(16) u64t sdup[TI_ * C_ * 4];  // {v,v} broadcast operands per (ii,c)
    float sraw[42 * 129];         // [r=c*3+d][j], pitch 129 (transpose pad)
    float ssq [C_ * L_];          // [c][j], poisoned if atom invalid
    float spart[2][TI_][L_];      // partial min d2 per atom-group
    int   sS[L_], sSeg[L_];
};
struct SmemEmbed {
    int sA[2][C_], sAP[2][C_];
};
union SmemAll { SmemFused f; SmemEmbed e; };

// ---------------------------------------------------------------------------
// Single kernel; blockIdx < FUSED_BLOCKS -> dist+knn+adj, else -> embed x2.
// ---------------------------------------------------------------------------
__global__ void __launch_bounds__(NT_, 4) mono_kernel(
        const float* __restrict__ X, const int* __restrict__ AP,
        const int* __restrict__ S, const int* __restrict__ seg,
        const int* __restrict__ RP, const int* __restrict__ A,
        const float* __restrict__ res_e, const float* __restrict__ atom_e,
        const float* __restrict__ atom_pe,
        float* __restrict__ out)
{
    __shared__ SmemAll sm;
    const int t = threadIdx.x;

    if (blockIdx.x >= FUSED_BLOCKS) {
        // ========== EMBED: 2 residues/block, thread = channel pair ==========
        const int nb   = blockIdx.x - FUSED_BLOCKS;
        const int half = t >> 7;
        const int e    = t & 127;                 // channel-pair index 0..127
        const int n    = nb * 2 + half;
        if (e < C_) { sm.e.sA[half][e] = A[n*C_ + e]; sm.e.sAP[half][e] = AP[n*C_ + e]; }
        __syncthreads();
        int cnt = 0;
        #pragma unroll
        for (int c = 0; c < C_; c++) cnt += (sm.e.sAP[half][c] != 0);
        float den = (float)cnt + 1e-10f;

        int   s  = S[n];
        float rp = (float)RP[n];
        float inv = exp2f(-(float)e * (13.287712379549449f / 128.0f));
        float ang = rp * inv;
        float sv, cv;
        __sincosf(ang, &sv, &cv);
        float2 re2 = *(const float2*)&res_e[s * E_ + 2*e];
        float2 o0; o0.x = re2.x + sv; o0.y = re2.y + cv;
        *(float2*)&out[OFF_H + (unsigned)n * 512u + 2*e] = o0;

        float accx = 0.0f, accy = 0.0f;
        #pragma unroll
        for (int c = 0; c < C_; c++) {
            int ap = sm.e.sAP[half][c];
            if (ap != 0) {
                float2 ae2 = *(const float2*)&atom_e [sm.e.sA[half][c] * E_ + 2*e];
                float2 pe2 = *(const float2*)&atom_pe[ap * E_ + 2*e];
                accx += ae2.x + pe2.x;
                accy += ae2.y + pe2.y;
            }
        }
        float2 o1; o1.x = accx / den; o1.y = accy / den;
        *(float2*)&out[OFF_H + (unsigned)n * 512u + 256u + 2*e] = o1;
        return;
    }

    // ================= FUSED dist + knn + adj ===============================
    const int b  = blockIdx.x / (L_ / TI_);
    const int i0 = (blockIdx.x % (L_ / TI_)) * TI_;
    const int g  = t >> 7;          // atom-group: 0 -> atoms 0..7, 1 -> atoms 8..13
    const int j  = t & 127;         // column
    const int lane = t & 31;
    const int wid  = t >> 5;

    // --- staging: float4 coalesced read of whole batch coords -> transpose ---
    {
        const float4* Xb4 = (const float4*)(X + (size_t)b * L_ * C_ * 3);
        #pragma unroll
        for (int k = 0; k < 6; k++) {
            int idx = k * NT_ + t;              // 1344 float4 total
            if (idx < 1344) {
                float4 v = Xb4[idx];
                int e0 = idx * 4;
                float vv[4] = {v.x, v.y, v.z, v.w};
                #pragma unroll
                for (int d = 0; d < 4; d++) {
                    int e2 = e0 + d;
                    int jj = e2 / 42;
                    int r  = e2 - jj * 42;
                    sm.f.sraw[r * 129 + jj] = vv[d];
                }
            }
        }
    }
    if (t < L_) {
        sm.f.sS[t]   = S[b * L_ + t];
        sm.f.sSeg[t] = seg[b * L_ + t];
    }
    __syncthreads();

    // --- per (group, column): own 4 atom-pairs into packed registers; ssq to smem ---
    u64t y0p[4], y1p[4], y2p[4], sjp[4];
    {
        const int cbase = g * 8;
        const int* apRow = AP + ((size_t)b * L_ + j) * C_;
        #pragma unroll
        for (int p = 0; p < 4; p++) {
            float a0l=0.f,a1l=0.f,a2l=0.f,sql=POISON;
            float a0h=0.f,a1h=0.f,a2h=0.f,sqh=POISON;
            int c0 = cbase + 2*p, c1 = c0 + 1;
            if (c0 < C_) {
                a0l = sm.f.sraw[(3*c0+0)*129 + j];
                a1l = sm.f.sraw[(3*c0+1)*129 + j];
                a2l = sm.f.sraw[(3*c0+2)*129 + j];
                float sq = (a0l*a0l + a1l*a1l) + a2l*a2l;
                sql = (apRow[c0] != 0) ? sq : POISON;
                sm.f.ssq[c0 * L_ + j] = sql;
            }
            if (c1 < C_) {
                a0h = sm.f.sraw[(3*c1+0)*129 + j];
                a1h = sm.f.sraw[(3*c1+1)*129 + j];
                a2h = sm.f.sraw[(3*c1+2)*129 + j];
                float sq = (a0h*a0h + a1h*a1h) + a2h*a2h;
                sqh = (apRow[c1] != 0) ? sq : POISON;
                sm.f.ssq[c1 * L_ + j] = sqh;
            }
            y0p[p] = pack2(a0l, a0h);
            y1p[p] = pack2(a1l, a1h);
            y2p[p] = pack2(a2l, a2h);
            sjp[p] = pack2(sql, sqh);
        }
    }
    __syncthreads();

    // --- build duplicated broadcast operands for the TI_ i-rows ---
    if (t < TI_ * C_) {
        int ii = t / C_, c = t % C_;
        int i  = i0 + ii;
        float v0 = sm.f.sraw[(3*c+0)*129 + i];
        float v1 = sm.f.sraw[(3*c+1)*129 + i];
        float v2 = sm.f.sraw[(3*c+2)*129 + i];
        float sq = sm.f.ssq[c * L_ + i];
        u64t* d = &sm.f.sdup[(ii * C_ + c) * 4];
        d[0] = pack2(v0, v0); d[1] = pack2(v1, v1);
        d[2] = pack2(v2, v2); d[3] = pack2(sq, sq);
    }
    __syncthreads();

    // --- hot loop: partial min over this group's atom pairs ---
    const u64t negtwo = pack2(-2.0f, -2.0f);
    #pragma unroll 2
    for (int ii = 0; ii < TI_; ii++) {
        float b0 = FLT_MAX, b1 = FLT_MAX, b2 = FLT_MAX, b3 = FLT_MAX;
        const ulonglong2* dup = (const ulonglong2*)&sm.f.sdup[ii * C_ * 4];
        #pragma unroll
        for (int c = 0; c < C_; c++) {
            ulonglong2 dA = dup[c*2 + 0];    // {xi0p, xi1p}  LDS.128 broadcast
            ulonglong2 dB = dup[c*2 + 1];    // {xi2p, sqcp}
            u64t xi0p = dA.x, xi1p = dA.y, xi2p = dB.x, sqcp = dB.y;
            #pragma unroll
            for (int p = 0; p < 4; p += 2) {
                {
                    u64t dot = fma2(xi2p, y2p[p], fma2(xi1p, y1p[p], mul2(xi0p, y0p[p])));
                    u64t d2  = fma2(dot, negtwo, add2(sqcp, sjp[p]));
                    float lo, hi;
                    unpack2(d2, lo, hi);          // register aliasing, no SASS op
                    b0 = fminf(b0, lo);
                    b1 = fminf(b1, hi);
                }
                {
                    u64t dot = fma2(xi2p, y2p[p+1], fma2(xi1p, y1p[p+1], mul2(xi0p, y0p[p+1])));
                    u64t d2  = fma2(dot, negtwo, add2(sqcp, sjp[p+1]));
                    float lo, hi;
                    unpack2(d2, lo, hi);
                    b2 = fminf(b2, lo);
                    b3 = fminf(b3, hi);
                }
            }
        }
        sm.f.spart[g][ii][j] = fminf(fminf(b0, b1), fminf(b2, b3));
    }

    // --- adj rows: thread (g, j) handles rows i0 + 2g, i0 + 2g + 1 ---
    {
        bool gj = is_glob(sm.f.sS[j]);
        int  segj = sm.f.sSeg[j];
        #pragma unroll
        for (int r2 = 0; r2 < 2; r2++) {
            int i = i0 + g * 2 + r2;
            bool gi = is_glob(sm.f.sS[i]);
            bool same = (sm.f.sSeg[i] == segj);
            bool ns   = (i != j);
            bool gn = same && (gi || gj) && ns;
            bool gg = gi && gj && ns;
            int  d  = i - j; if (d < 0) d = -d;
            bool sme = (d == 1) && !gi && !gj && (sm.f.sSeg[i] != 1);
            out[OFF_ADJ + ((unsigned)(b * L_ + i)) * L_ + j] = (gn || gg || sme) ? 1.0f : 0.0f;
        }
    }
    __syncthreads();

    // --- knn: 2*TI_ = 8 warp tasks (all 8 warps, one round, REDUX argmin) ---
    {
        const unsigned BIGB = __float_as_uint(BIGF);
        int ii   = wid >> 1;
        int type = wid & 1;                  // 0 = ctx (inner), 1 = inter (outer)
        int i    = i0 + ii;
        int r    = b * L_ + i;
        bool gi  = is_glob(sm.f.sS[i]);
        int  si  = sm.f.sSeg[i];

        unsigned u0, u1, u2, u3;
        {
            unsigned uu[4];
            #pragma unroll
            for (int s2 = 0; s2 < 4; s2++) {
                int jj = lane + 32 * s2;
                bool gj   = is_glob(sm.f.sS[jj]);
                bool same = (sm.f.sSeg[jj] == si);
                bool m;
                if (type == 0) m = same && !gi && !gj && (jj != i);
                else           m = !same && !gi && !gj;
                float d2 = fminf(sm.f.spart[0][ii][jj], sm.f.spart[1][ii][jj]);
                float dv = sqrtf(fmaxf(d2, 0.0f));
                uu[s2] = m ? __float_as_uint(dv) : BIGB;
            }
            u0 = uu[0]; u1 = uu[1]; u2 = uu[2]; u3 = uu[3];
        }

        unsigned offK = type ? OFF_INT_KNN   : OFF_CTX_KNN;
        unsigned offV = type ? OFF_INT_VALID : OFF_CTX_VALID;

        #pragma unroll
        for (int k = 0; k < K_; k++) {
            unsigned m    = min(min(u0, u1), min(u2, u3));
            unsigned wmin = __reduce_min_sync(0xffffffffu, m);
            unsigned jc = 256u;
            if (u3 == wmin) jc = (unsigned)lane + 96u;
            if (u2 == wmin) jc = (unsigned)lane + 64u;
            if (u1 == wmin) jc = (unsigned)lane + 32u;
            if (u0 == wmin) jc = (unsigned)lane;
            unsigned jw = __reduce_min_sync(0xffffffffu, jc);
            unsigned s  = jw >> 5;
            bool own = (jc == jw);
            u0 = (own && s == 0u) ? 0xFFFFFFFFu : u0;
            u1 = (own && s == 1u) ? 0xFFFFFFFFu : u1;
            u2 = (own && s == 2u) ? 0xFFFFFFFFu : u2;
            u3 = (own && s == 3u) ? 0xFFFFFFFFu : u3;
            if (lane == 0) {
                bool valid = wmin < BIGB;
                out[offK + (unsigned)r * K_ + k]            = valid ? (float)r                : -1.0f;
                out[offK + KNN_ROWS + (unsigned)r * K_ + k] = valid ? (float)(b*L_ + (int)jw) : -1.0f;
                out[offV + (unsigned)r * K_ + k]            = valid ? 1.0f : 0.0f;
            }
        }
    }
}

// ---------------------------------------------------------------------------
extern "C" void kernel_launch(void* const* d_in, const int* in_sizes, int n_in,
                              void* d_out, int out_size)
{
    const int*   S   = (const int*)  d_in[0];
    const int*   RP  = (const int*)  d_in[1];
    const int*   A   = (const int*)  d_in[2];
    const int*   AP  = (const int*)  d_in[3];
    const float* X   = (const float*)d_in[4];
    const int*   seg = (const int*)  d_in[5];
    const float* re  = (const float*)d_in[6];
    const float* ae  = (const float*)d_in[7];
    const float* ape = (const float*)d_in[8];
    float* out = (float*)d_out;

    mono_kernel<<<FUSED_BLOCKS + EMBED_BLOCKS, NT_>>>(X, AP, S, seg, RP, A, re, ae, ape, out);
}